// round 11
// baseline (speedup 1.0000x reference)
#include <cuda_runtime.h>
#include <stdint.h>

// Problem constants (from reference)
#define GX 352
#define GY 400
#define GZ 1
#define NB 4
#define NSEG (NB * GZ * GY * GX)    // 563200
#define NC 4
#define NP 2000000

// Output layout: [mean: NSEG*NC floats][counts: NSEG floats]
#define OUT_TOTAL (NSEG * (NC + 1)) // 2816000 floats

// ---------------------------------------------------------------------------
// Persistent scratch accumulator. Zero-initialized at module load; the divide
// kernel consumes it via atom.exch (read old + write 0 in ONE transaction),
// restoring the all-zeros invariant for the next graph replay. Deterministic,
// no memset pass.
//   [0 .. NSEG*4)          per-segment feature sums (float4 per seg)
//   [NSEG*4 .. NSEG*5)     per-segment counts
// ---------------------------------------------------------------------------
__device__ float g_scratch[NSEG * (NC + 1)];

__device__ __forceinline__ void red_add_v4(float* dst, float4 f) {
    asm volatile("red.global.add.v4.f32 [%0], {%1, %2, %3, %4};"
                 :: "l"(dst), "f"(f.x), "f"(f.y), "f"(f.z), "f"(f.w)
                 : "memory");
}
__device__ __forceinline__ void red_add_1(float* dst) {
    asm volatile("red.global.add.f32 [%0], %1;"
                 :: "l"(dst), "f"(1.0f) : "memory");
}

// ---------------------------------------------------------------------------
// Scatter-add: one point per thread (measured best; at the L2-atomic floor).
// GZ == 1 -> seg = (b*GY + y)*GX + x.
// ---------------------------------------------------------------------------
__global__ void __launch_bounds__(256)
scatter_add_kernel(const float4* __restrict__ features,
                   const int4*   __restrict__ coors) {
    int i = blockIdx.x * blockDim.x + threadIdx.x;
    if (i >= NP) return;

    int4   c = coors[i];                       // (b, z, y, x)
    float4 f = features[i];
    int seg = (c.x * GY + c.z) * GX + c.w;

    red_add_v4(g_scratch + (size_t)seg * NC, f);
    red_add_1(g_scratch + NSEG * NC + seg);
}

// ---------------------------------------------------------------------------
// Divide + emit + scratch-restore: one segment per thread.
// Consume-and-reset via atomic exchange:
//   2x atom.exch.b64  -> old sums (16B) read + zeroed in 2 L2 transactions
//   1x atom.exch.b32  -> old count read + zeroed in 1 transaction
// then compute mean and store mean+count to d_out.
// ---------------------------------------------------------------------------
__global__ void __launch_bounds__(256)
divide_kernel(float* __restrict__ out) {
    int seg = blockIdx.x * blockDim.x + threadIdx.x;
    if (seg >= NSEG) return;

    float* sbase = g_scratch + (size_t)seg * NC;
    float* cbase = g_scratch + (size_t)NSEG * NC + seg;

    unsigned long long z64 = 0ULL, o01, o23;
    unsigned int z32 = 0u, oc;

    // front-batched independent atomics (MLP=3)
    asm volatile("atom.global.exch.b64 %0, [%1], %2;"
                 : "=l"(o01) : "l"(sbase), "l"(z64) : "memory");
    asm volatile("atom.global.exch.b64 %0, [%1], %2;"
                 : "=l"(o23) : "l"(sbase + 2), "l"(z64) : "memory");
    asm volatile("atom.global.exch.b32 %0, [%1], %2;"
                 : "=r"(oc) : "l"(cbase), "r"(z32) : "memory");

    float s0 = __uint_as_float((unsigned int)(o01 & 0xffffffffu));
    float s1 = __uint_as_float((unsigned int)(o01 >> 32));
    float s2 = __uint_as_float((unsigned int)(o23 & 0xffffffffu));
    float s3 = __uint_as_float((unsigned int)(o23 >> 32));
    float cnt = __uint_as_float(oc);

    float inv = 1.0f / fmaxf(cnt, 1.0f);
    float4 m;
    m.x = s0 * inv; m.y = s1 * inv; m.z = s2 * inv; m.w = s3 * inv;

    ((float4*)out)[seg]  = m;     // mean region
    out[NSEG * NC + seg] = cnt;   // counts region
}

// ---------------------------------------------------------------------------
// Launcher: two kernels, no memset node.
// ---------------------------------------------------------------------------
extern "C" void kernel_launch(void* const* d_in, const int* in_sizes, int n_in,
                              void* d_out, int out_size) {
    const float4* features = (const float4*)d_in[0];  // (NP, 4) fp32
    const int4*   coors    = (const int4*)d_in[1];    // (NP, 4) int32
    float* out = (float*)d_out;

    {
        int threads = 256;
        int blocks = (NP + threads - 1) / threads;
        scatter_add_kernel<<<blocks, threads>>>(features, coors);
    }
    {
        int threads = 256;
        int blocks = (NSEG + threads - 1) / threads;
        divide_kernel<<<blocks, threads>>>(out);
    }
}

// round 12
// speedup vs baseline: 1.0826x; 1.0826x over previous
#include <cuda_runtime.h>
#include <stdint.h>

// Problem constants (from reference)
#define GX 352
#define GY 400
#define GZ 1
#define NB 4
#define NSEG (NB * GZ * GY * GX)    // 563200
#define NC 4
#define NP 2000000

// Output layout: [mean: NSEG*NC floats][counts: NSEG floats]
#define OUT_TOTAL (NSEG * (NC + 1)) // 2816000 floats

// ---------------------------------------------------------------------------
// Persistent scratch accumulator. Zero-initialized at module load; the divide
// kernel restores the all-zeros invariant after consuming it, so every graph
// replay starts from zeros -> deterministic, and NO memset pass is needed.
//   [0 .. NSEG*4)          per-segment feature sums (float4 per seg)
//   [NSEG*4 .. NSEG*5)     per-segment counts
// ---------------------------------------------------------------------------
__device__ float g_scratch[NSEG * (NC + 1)];

__device__ __forceinline__ void red_add_v4(float* dst, float4 f) {
    asm volatile("red.global.add.v4.f32 [%0], {%1, %2, %3, %4};"
                 :: "l"(dst), "f"(f.x), "f"(f.y), "f"(f.z), "f"(f.w)
                 : "memory");
}
__device__ __forceinline__ void red_add_1(float* dst) {
    asm volatile("red.global.add.f32 [%0], %1;"
                 :: "l"(dst), "f"(1.0f) : "memory");
}

// ---------------------------------------------------------------------------
// Scatter-add: one point per thread (measured best; at the L2-atomic floor:
// 5 dword accumulations/point is the semantic minimum).
// GZ == 1 -> seg = (b*GY + y)*GX + x.
// ---------------------------------------------------------------------------
__global__ void __launch_bounds__(256)
scatter_add_kernel(const float4* __restrict__ features,
                   const int4*   __restrict__ coors) {
    int i = blockIdx.x * blockDim.x + threadIdx.x;
    if (i >= NP) return;

    int4   c = coors[i];                       // (b, z, y, x)
    float4 f = features[i];
    int seg = (c.x * GY + c.z) * GX + c.w;

    red_add_v4(g_scratch + (size_t)seg * NC, f);
    red_add_1(g_scratch + NSEG * NC + seg);
}

// ---------------------------------------------------------------------------
// Divide + emit + scratch-restore: one segment per thread (best-measured
// divide config: regs=23, occ=74%). Launched with PDL: blocks come up and do
// index math while scatter drains; cudaGridDependencySynchronize() gates the
// scratch reads on scatter's completed memory flush.
// ---------------------------------------------------------------------------
__global__ void __launch_bounds__(256)
divide_kernel(float* __restrict__ out) {
    int seg = blockIdx.x * blockDim.x + threadIdx.x;

    // Wait for the upstream (scatter) grid's memory to be visible.
    cudaGridDependencySynchronize();

    if (seg >= NSEG) return;

    float4* s_sums   = (float4*)g_scratch;
    float*  s_counts = g_scratch + NSEG * NC;

    float4 s   = s_sums[seg];
    float  cnt = s_counts[seg];

    float inv = 1.0f / fmaxf(cnt, 1.0f);
    float4 m;
    m.x = s.x * inv; m.y = s.y * inv; m.z = s.z * inv; m.w = s.w * inv;

    ((float4*)out)[seg]  = m;     // mean region
    out[NSEG * NC + seg] = cnt;   // counts region

    // restore scratch to zero for the next graph replay
    s_sums[seg]   = make_float4(0.f, 0.f, 0.f, 0.f);
    s_counts[seg] = 0.0f;
}

// ---------------------------------------------------------------------------
// Launcher: scatter, then divide via programmatic dependent launch.
// ---------------------------------------------------------------------------
extern "C" void kernel_launch(void* const* d_in, const int* in_sizes, int n_in,
                              void* d_out, int out_size) {
    const float4* features = (const float4*)d_in[0];  // (NP, 4) fp32
    const int4*   coors    = (const int4*)d_in[1];    // (NP, 4) int32
    float* out = (float*)d_out;

    // 1. scatter-add
    {
        int threads = 256;
        int blocks = (NP + threads - 1) / threads;
        scatter_add_kernel<<<blocks, threads>>>(features, coors);
    }

    // 2. divide, launched programmatically-dependent on the scatter
    {
        int threads = 256;
        int blocks = (NSEG + threads - 1) / threads;

        cudaLaunchConfig_t cfg = {};
        cfg.gridDim  = dim3(blocks, 1, 1);
        cfg.blockDim = dim3(threads, 1, 1);
        cfg.dynamicSmemBytes = 0;
        cfg.stream = 0;

        cudaLaunchAttribute attrs[1];
        attrs[0].id = cudaLaunchAttributeProgrammaticStreamSerialization;
        attrs[0].val.programmaticStreamSerializationAllowed = 1;
        cfg.attrs = attrs;
        cfg.numAttrs = 1;

        cudaLaunchKernelEx(&cfg, divide_kernel, out);
    }
}